// round 3
// baseline (speedup 1.0000x reference)
#include <cuda_runtime.h>
#include <math.h>

#define HWSZ 16384
#define IMG  128
#define BATCH 8

// -------- scratch (static device memory; no runtime allocation) ------------
// Aliased buffers (all kernels sequential on one stream):
//   slot A (BUF64): q        -> lc
//   slot B (BUF64): keypre   -> v   -> u
//   slot C (BUF64): key      (live whole pipeline)
//   slot T (BUF32): t32      (embed hidden, used twice)
//   slot W (BUF72): w72      -> attn
#define BUF64 8388608ull   // 8*64*16384
#define BUF32 4194304ull
#define BUF72 9437184ull
static __device__ float g_scratch[3*BUF64 + BUF32 + BUF72];

// ---------------------------------------------------------------------------
// Generic 1x1-conv GEMM:  out[b,m,p] = act( sum_k W[m,k] * in[b,k,p] + bias )
// Input channels may be split across two tensors (concat without materializing).
// Tile: MTILE x 128 pixels, register block MR x 4, K chunked by 32.
// ---------------------------------------------------------------------------
template<int KC, int MTILE, int MR, int SPLIT, int ACT>
__global__ void __launch_bounds__((MTILE/MR)*32)
conv1x1_kernel(float* __restrict__ out, const float* __restrict__ in0,
               const float* __restrict__ in1, const float* __restrict__ Wt,
               const float* __restrict__ bias, int Mtot)
{
    constexpr int NT = (MTILE/MR)*32;
    __shared__ __align__(16) float sIn[32][128];
    __shared__ __align__(16) float sW[KC][MTILE];
    const int tid = threadIdx.x;
    const int b   = blockIdx.y;
    const int p0  = blockIdx.x * 128;
    const int m0  = blockIdx.z * MTILE;

    // whole weight tile resident once, layout [k][m]
    for (int i = tid; i < KC*MTILE; i += NT) {
        int k = i / MTILE, m = i - k*MTILE;
        sW[k][m] = Wt[(m0 + m)*KC + k];
    }

    const int row = tid >> 5, col = tid & 31;
    float acc[MR][4];
    #pragma unroll
    for (int i = 0; i < MR; i++)
        #pragma unroll
        for (int j = 0; j < 4; j++) acc[i][j] = 0.f;

    for (int kc0 = 0; kc0 < KC; kc0 += 32) {
        __syncthreads();          // covers weight load (iter 0) and sIn reuse
        for (int i = tid; i < 1024; i += NT) {   // 32 k x 32 float4
            int k = i >> 5, p4 = i & 31;
            int kg = kc0 + k;
            const float* src;
            if (kg < SPLIT) src = in0 + ((size_t)b*SPLIT + kg)*HWSZ;
            else            src = in1 + ((size_t)b*(KC-SPLIT) + (kg-SPLIT))*HWSZ;
            ((float4*)sIn)[i] = *(const float4*)&src[p0 + p4*4];
        }
        __syncthreads();
        #pragma unroll
        for (int kk = 0; kk < 32; kk++) {
            float4 bv = *(const float4*)&sIn[kk][col*4];
            float a[MR];
            #pragma unroll
            for (int i = 0; i < MR; i += 4)
                *(float4*)&a[i] = *(const float4*)&sW[kc0+kk][row*MR + i];
            #pragma unroll
            for (int i = 0; i < MR; i++) {
                acc[i][0] += a[i]*bv.x;
                acc[i][1] += a[i]*bv.y;
                acc[i][2] += a[i]*bv.z;
                acc[i][3] += a[i]*bv.w;
            }
        }
    }

    #pragma unroll
    for (int i = 0; i < MR; i++) {
        int m = m0 + row*MR + i;
        float bb = bias ? bias[m] : 0.f;
        float4 o;
        o.x = acc[i][0]+bb; o.y = acc[i][1]+bb;
        o.z = acc[i][2]+bb; o.w = acc[i][3]+bb;
        if (ACT) {
            o.x = o.x > 0.f ? o.x : 0.1f*o.x;
            o.y = o.y > 0.f ? o.y : 0.1f*o.y;
            o.z = o.z > 0.f ? o.z : 0.1f*o.z;
            o.w = o.w > 0.f ? o.w : 0.1f*o.w;
        }
        *(float4*)&out[((size_t)b*Mtot + m)*HWSZ + p0 + col*4] = o;
    }
}

// ---------------------------------------------------------------------------
// Grouped 3x3 conv (groups=4, 16 in/16 out per group), pad 1, + leaky relu.
// One block = (b, group, 16x16 spatial tile). Weights packed [ci][tap][co].
// ---------------------------------------------------------------------------
__global__ void __launch_bounds__(256)
convke_kernel(float* __restrict__ out, const float* __restrict__ in,
              const float* __restrict__ w)
{
    const int tid = threadIdx.x;
    const int b = blockIdx.z >> 2, g = blockIdx.z & 3;
    const int x0 = blockIdx.x * 16, y0 = blockIdx.y * 16;
    __shared__ __align__(16) float sv[16][18][18];
    __shared__ __align__(16) float swt[16][9][16];

    for (int i = tid; i < 16*16*9; i += 256) {
        int co = i / 144; int r = i - co*144; int ci = r / 9; int tap = r - ci*9;
        swt[ci][tap][co] = w[((g*16 + co)*16 + ci)*9 + tap];
    }
    for (int i = tid; i < 16*324; i += 256) {
        int ci = i / 324; int r = i - ci*324; int yy = r / 18; int xx = r - yy*18;
        int gy = y0 + yy - 1, gx = x0 + xx - 1;
        float v = 0.f;
        if ((unsigned)gy < 128u && (unsigned)gx < 128u)
            v = in[(((size_t)b*64 + g*16 + ci)*IMG + gy)*IMG + gx];
        sv[ci][yy][xx] = v;
    }
    __syncthreads();

    const int ty = tid >> 4, tx = tid & 15;
    float acc[16];
    #pragma unroll
    for (int c = 0; c < 16; c++) acc[c] = 0.f;

    #pragma unroll
    for (int ci = 0; ci < 16; ci++) {
        float win[9];
        #pragma unroll
        for (int t = 0; t < 9; t++) win[t] = sv[ci][ty + t/3][tx + t%3];
        #pragma unroll
        for (int t = 0; t < 9; t++) {
            #pragma unroll
            for (int q = 0; q < 4; q++) {
                float4 wq = *(const float4*)&swt[ci][t][q*4];
                acc[q*4+0] += win[t]*wq.x;
                acc[q*4+1] += win[t]*wq.y;
                acc[q*4+2] += win[t]*wq.z;
                acc[q*4+3] += win[t]*wq.w;
            }
        }
    }
    #pragma unroll
    for (int co = 0; co < 16; co++) {
        float v = acc[co]; v = v > 0.f ? v : 0.1f*v;
        out[(((size_t)b*64 + g*16 + co)*IMG + y0+ty)*IMG + x0+tx] = v;
    }
}

// ---------------------------------------------------------------------------
// Per-pixel dynamic local conv: out[b,cg*8+s,p] = sum_t v[...,p+off(t)] * wd[b,cg*9+t,p]
// Second instance fuses residual add (writes final d_out).
// ---------------------------------------------------------------------------
template<bool RESID>
__global__ void __launch_bounds__(256)
localconv_kernel(float* __restrict__ out, const float* __restrict__ v,
                 const float* __restrict__ wd, const float* __restrict__ resid)
{
    const int tid = threadIdx.x;
    const int b = blockIdx.z >> 3, cg = blockIdx.z & 7;
    const int x0 = blockIdx.x * 16, y0 = blockIdx.y * 16;
    __shared__ float sv[8][18][18];

    for (int i = tid; i < 8*324; i += 256) {
        int cl = i / 324; int r = i - cl*324; int yy = r / 18; int xx = r - yy*18;
        int gy = y0 + yy - 1, gx = x0 + xx - 1;
        float val = 0.f;
        if ((unsigned)gy < 128u && (unsigned)gx < 128u)
            val = v[(((size_t)b*64 + cg*8 + cl)*IMG + gy)*IMG + gx];
        sv[cl][yy][xx] = val;
    }
    __syncthreads();

    const int ty = tid >> 4, tx = tid & 15;
    float wt[9];
    #pragma unroll
    for (int t = 0; t < 9; t++)
        wt[t] = wd[(((size_t)b*72 + cg*9 + t)*IMG + y0+ty)*IMG + x0+tx];

    #pragma unroll
    for (int cl = 0; cl < 8; cl++) {
        float a = 0.f;
        #pragma unroll
        for (int t = 0; t < 9; t++) a += sv[cl][ty + t/3][tx + t%3]*wt[t];
        size_t oi = (((size_t)b*64 + cg*8 + cl)*IMG + y0+ty)*IMG + x0+tx;
        out[oi] = RESID ? (a + resid[oi]) : a;
    }
}

// ---------------------------------------------------------------------------
// Softmax over H (axis 2 of [B,72,H,W]) in place. Block (32,8) covers 32 w
// columns x all 128 h. Coalesced loads; two smem reductions (max, sum).
// ---------------------------------------------------------------------------
__global__ void softmaxH_kernel(float* __restrict__ a)
{
    const int tx = threadIdx.x, ty = threadIdx.y;
    const int w = blockIdx.x*32 + tx;
    const size_t base = (size_t)blockIdx.y * HWSZ + w;   // blockIdx.y = b*72+cc
    float vals[16];
    float mx = -3.4e38f;
    #pragma unroll
    for (int i = 0; i < 16; i++) {
        vals[i] = a[base + (size_t)(ty*16 + i)*IMG];
        mx = fmaxf(mx, vals[i]);
    }
    __shared__ float red[8][32];
    red[ty][tx] = mx;
    __syncthreads();
    float m = red[0][tx];
    #pragma unroll
    for (int j = 1; j < 8; j++) m = fmaxf(m, red[j][tx]);
    __syncthreads();
    float s = 0.f;
    #pragma unroll
    for (int i = 0; i < 16; i++) { vals[i] = __expf(vals[i] - m); s += vals[i]; }
    red[ty][tx] = s;
    __syncthreads();
    float tot = 0.f;
    #pragma unroll
    for (int j = 0; j < 8; j++) tot += red[j][tx];
    float inv = 1.f / tot;
    #pragma unroll
    for (int i = 0; i < 16; i++)
        a[base + (size_t)(ty*16 + i)*IMG] = vals[i]*inv;
}

// ---------------------------------------------------------------------------
extern "C" void kernel_launch(void* const* d_in, const int* in_sizes, int n_in,
                              void* d_out, int out_size)
{
    const float* x      = (const float*)d_in[0];
    const float* phi_w  = (const float*)d_in[1];
    const float* phi_b  = (const float*)d_in[2];
    const float* theta_w= (const float*)d_in[3];
    const float* theta_b= (const float*)d_in[4];
    const float* ke_w   = (const float*)d_in[5];
    const float* e1_w   = (const float*)d_in[6];
    const float* e2_w   = (const float*)d_in[7];
    const float* e2_b   = (const float*)d_in[8];
    const float* c1_w   = (const float*)d_in[9];
    const float* sw1_w  = (const float*)d_in[10];
    const float* sw2_w  = (const float*)d_in[11];
    const float* sw2_b  = (const float*)d_in[12];
    const float* sec_w  = (const float*)d_in[13];
    const float* sec_b  = (const float*)d_in[14];
    float* out = (float*)d_out;

    float* base = nullptr;
    cudaGetSymbolAddress((void**)&base, g_scratch);
    // Aliased slots (lifetimes disjoint; launches are stream-ordered):
    float* slotA = base;                 // q, then lc
    float* slotB = base + BUF64;         // keypre, then v, then u
    float* key   = base + 2*BUF64;       // live whole pipeline
    float* t32   = base + 3*BUF64;       // embed hidden (used twice)
    float* slotW = t32 + BUF32;          // w72, then attn

    float* q      = slotA;
    float* lc     = slotA;
    float* keypre = slotB;
    float* v      = slotB;
    float* u      = slotB;
    float* w72    = slotW;
    float* attn   = slotW;

    dim3 g64(128, 8, 1);
    // key_pre = phi(x), query = theta(x)
    conv1x1_kernel<64,64,8,64,0><<<g64,256>>>(keypre, x, nullptr, phi_w, phi_b, 64);
    conv1x1_kernel<64,64,8,64,0><<<g64,256>>>(q,      x, nullptr, theta_w, theta_b, 64);
    // key = lrelu(grouped 3x3(key_pre))
    convke_kernel<<<dim3(8,8,32),256>>>(key, keypre, ke_w);
    // dynamic kernel 1: w72 = e2(lrelu(e1([query;key])))   (q dead after this)
    conv1x1_kernel<128,32,4,64,1><<<g64,256>>>(t32, q, key, e1_w, nullptr, 32);
    conv1x1_kernel<32,36,4,32,0><<<dim3(128,8,2),288>>>(w72, t32, nullptr, e2_w, e2_b, 72);
    // h(first half) = local_conv(c1(x), w72)   (keypre dead; v reuses slotB)
    conv1x1_kernel<64,64,8,64,0><<<g64,256>>>(v, x, nullptr, c1_w, nullptr, 64);
    localconv_kernel<false><<<dim3(8,8,64),256>>>(lc, v, w72, nullptr);
    // attention weights: attn = softmax_H(sw2(lrelu(sw1([lc;key]))))
    conv1x1_kernel<128,32,4,64,1><<<g64,256>>>(t32, lc, key, sw1_w, nullptr, 32);
    conv1x1_kernel<32,36,4,32,0><<<dim3(128,8,2),288>>>(attn, t32, nullptr, sw2_w, sw2_b, 72);
    softmaxH_kernel<<<dim3(4, 8*72), dim3(32,8)>>>(attn);
    // out = local_conv(sec([lc;key]), attn) + x   (v dead; u reuses slotB)
    conv1x1_kernel<128,64,8,64,0><<<g64,256>>>(u, lc, key, sec_w, sec_b, 64);
    localconv_kernel<true><<<dim3(8,8,64),256>>>(out, u, attn, x);
}

// round 4
// speedup vs baseline: 1.1016x; 1.1016x over previous
#include <cuda_runtime.h>
#include <math.h>

#define HWSZ 16384
#define IMG  128
#define BATCH 8

// -------- scratch (static device memory; no runtime allocation) ------------
// Aliased buffers (all kernels sequential on one stream):
//   slot A (BUF64): q        -> lc
//   slot B (BUF64): keypre   -> v   -> u
//   slot C (BUF64): key      (live whole pipeline)
//   slot T (BUF32): t32      (embed hidden, used twice)
//   slot W (BUF72): w72      -> attn
#define BUF64 8388608ull   // 8*64*16384
#define BUF32 4194304ull
#define BUF72 9437184ull
static __device__ float g_scratch[3*BUF64 + BUF32 + BUF72];

// ---------------------------------------------------------------------------
// 1x1-conv GEMM v2: out[b,m,p] = act( sum_k W[m,k]*in[b,k,p] + bias )
// Block tile: MTILE rows x 256 pixels. Thread tile: 8 rows x 8 pixels.
// One warp owns 8 rows x 256 pixels (weights are warp-uniform -> smem
// broadcast). K chunked by 32. smem: sIn 32KB + sW 32*MTILE*4.
// Inner kk: 2 broadcast LDS.128 (weights) + 2 LDS.128 (pixels) per thread
// for 64 FMA -> FMA-pipe bound (was smem-bound at 4x4 tile).
// ---------------------------------------------------------------------------
template<int KC, int MTILE, int SPLIT, int ACT>
__global__ void __launch_bounds__((MTILE/8)*32, 1)
conv1x1v2_kernel(float* __restrict__ out, const float* __restrict__ in0,
                 const float* __restrict__ in1, const float* __restrict__ Wt,
                 const float* __restrict__ bias, int Mtot)
{
    constexpr int NT = (MTILE/8)*32;
    __shared__ __align__(16) float sIn[32][256];
    __shared__ __align__(16) float sW[32][MTILE];
    const int tid  = threadIdx.x;
    const int b    = blockIdx.y;
    const int p0   = blockIdx.x * 256;
    const int m0   = blockIdx.z * MTILE;
    const int warp = tid >> 5, col = tid & 31;

    float acc[8][8];
    #pragma unroll
    for (int i = 0; i < 8; i++)
        #pragma unroll
        for (int j = 0; j < 8; j++) acc[i][j] = 0.f;

    for (int kc0 = 0; kc0 < KC; kc0 += 32) {
        __syncthreads();   // protect smem reuse from previous chunk
        // weights chunk [kk][m]
        for (int i = tid; i < 32*MTILE; i += NT) {
            int k = i / MTILE, m = i - k*MTILE;
            sW[k][m] = Wt[(m0 + m)*KC + kc0 + k];
        }
        // input chunk: 32 k x 64 float4 (coalesced: warp covers 512B runs)
        for (int i = tid; i < 2048; i += NT) {
            int k = i >> 6, p4 = i & 63;
            int kg = kc0 + k;
            const float* src;
            if (kg < SPLIT) src = in0 + ((size_t)b*SPLIT + kg)*HWSZ;
            else            src = in1 + ((size_t)b*(KC-SPLIT) + (kg-SPLIT))*HWSZ;
            ((float4*)sIn)[i] = *(const float4*)&src[p0 + p4*4];
        }
        __syncthreads();

        #pragma unroll 4
        for (int kk = 0; kk < 32; kk++) {
            float4 a0 = *(const float4*)&sIn[kk][col*4];
            float4 a1 = *(const float4*)&sIn[kk][col*4 + 128];
            float w[8];
            *(float4*)&w[0] = *(const float4*)&sW[kk][warp*8];
            *(float4*)&w[4] = *(const float4*)&sW[kk][warp*8 + 4];
            #pragma unroll
            for (int i = 0; i < 8; i++) {
                acc[i][0] += w[i]*a0.x;  acc[i][1] += w[i]*a0.y;
                acc[i][2] += w[i]*a0.z;  acc[i][3] += w[i]*a0.w;
                acc[i][4] += w[i]*a1.x;  acc[i][5] += w[i]*a1.y;
                acc[i][6] += w[i]*a1.z;  acc[i][7] += w[i]*a1.w;
            }
        }
    }

    #pragma unroll
    for (int i = 0; i < 8; i++) {
        int m = m0 + warp*8 + i;
        float bb = bias ? bias[m] : 0.f;
        float4 o0, o1;
        o0.x = acc[i][0]+bb; o0.y = acc[i][1]+bb;
        o0.z = acc[i][2]+bb; o0.w = acc[i][3]+bb;
        o1.x = acc[i][4]+bb; o1.y = acc[i][5]+bb;
        o1.z = acc[i][6]+bb; o1.w = acc[i][7]+bb;
        if (ACT) {
            o0.x = o0.x > 0.f ? o0.x : 0.1f*o0.x;
            o0.y = o0.y > 0.f ? o0.y : 0.1f*o0.y;
            o0.z = o0.z > 0.f ? o0.z : 0.1f*o0.z;
            o0.w = o0.w > 0.f ? o0.w : 0.1f*o0.w;
            o1.x = o1.x > 0.f ? o1.x : 0.1f*o1.x;
            o1.y = o1.y > 0.f ? o1.y : 0.1f*o1.y;
            o1.z = o1.z > 0.f ? o1.z : 0.1f*o1.z;
            o1.w = o1.w > 0.f ? o1.w : 0.1f*o1.w;
        }
        size_t ob = ((size_t)b*Mtot + m)*HWSZ + p0;
        *(float4*)&out[ob + col*4]       = o0;
        *(float4*)&out[ob + col*4 + 128] = o1;
    }
}

// ---------------------------------------------------------------------------
// Grouped 3x3 conv (groups=4, 16 in/16 out per group), pad 1, + leaky relu.
// ---------------------------------------------------------------------------
__global__ void __launch_bounds__(256)
convke_kernel(float* __restrict__ out, const float* __restrict__ in,
              const float* __restrict__ w)
{
    const int tid = threadIdx.x;
    const int b = blockIdx.z >> 2, g = blockIdx.z & 3;
    const int x0 = blockIdx.x * 16, y0 = blockIdx.y * 16;
    __shared__ __align__(16) float sv[16][18][18];
    __shared__ __align__(16) float swt[16][9][16];

    for (int i = tid; i < 16*16*9; i += 256) {
        int co = i / 144; int r = i - co*144; int ci = r / 9; int tap = r - ci*9;
        swt[ci][tap][co] = w[((g*16 + co)*16 + ci)*9 + tap];
    }
    for (int i = tid; i < 16*324; i += 256) {
        int ci = i / 324; int r = i - ci*324; int yy = r / 18; int xx = r - yy*18;
        int gy = y0 + yy - 1, gx = x0 + xx - 1;
        float v = 0.f;
        if ((unsigned)gy < 128u && (unsigned)gx < 128u)
            v = in[(((size_t)b*64 + g*16 + ci)*IMG + gy)*IMG + gx];
        sv[ci][yy][xx] = v;
    }
    __syncthreads();

    const int ty = tid >> 4, tx = tid & 15;
    float acc[16];
    #pragma unroll
    for (int c = 0; c < 16; c++) acc[c] = 0.f;

    #pragma unroll
    for (int ci = 0; ci < 16; ci++) {
        float win[9];
        #pragma unroll
        for (int t = 0; t < 9; t++) win[t] = sv[ci][ty + t/3][tx + t%3];
        #pragma unroll
        for (int t = 0; t < 9; t++) {
            #pragma unroll
            for (int q = 0; q < 4; q++) {
                float4 wq = *(const float4*)&swt[ci][t][q*4];
                acc[q*4+0] += win[t]*wq.x;
                acc[q*4+1] += win[t]*wq.y;
                acc[q*4+2] += win[t]*wq.z;
                acc[q*4+3] += win[t]*wq.w;
            }
        }
    }
    #pragma unroll
    for (int co = 0; co < 16; co++) {
        float v = acc[co]; v = v > 0.f ? v : 0.1f*v;
        out[(((size_t)b*64 + g*16 + co)*IMG + y0+ty)*IMG + x0+tx] = v;
    }
}

// ---------------------------------------------------------------------------
// Per-pixel dynamic local conv. Second instance fuses residual add.
// ---------------------------------------------------------------------------
template<bool RESID>
__global__ void __launch_bounds__(256)
localconv_kernel(float* __restrict__ out, const float* __restrict__ v,
                 const float* __restrict__ wd, const float* __restrict__ resid)
{
    const int tid = threadIdx.x;
    const int b = blockIdx.z >> 3, cg = blockIdx.z & 7;
    const int x0 = blockIdx.x * 16, y0 = blockIdx.y * 16;
    __shared__ float sv[8][18][18];

    for (int i = tid; i < 8*324; i += 256) {
        int cl = i / 324; int r = i - cl*324; int yy = r / 18; int xx = r - yy*18;
        int gy = y0 + yy - 1, gx = x0 + xx - 1;
        float val = 0.f;
        if ((unsigned)gy < 128u && (unsigned)gx < 128u)
            val = v[(((size_t)b*64 + cg*8 + cl)*IMG + gy)*IMG + gx];
        sv[cl][yy][xx] = val;
    }
    __syncthreads();

    const int ty = tid >> 4, tx = tid & 15;
    float wt[9];
    #pragma unroll
    for (int t = 0; t < 9; t++)
        wt[t] = wd[(((size_t)b*72 + cg*9 + t)*IMG + y0+ty)*IMG + x0+tx];

    #pragma unroll
    for (int cl = 0; cl < 8; cl++) {
        float a = 0.f;
        #pragma unroll
        for (int t = 0; t < 9; t++) a += sv[cl][ty + t/3][tx + t%3]*wt[t];
        size_t oi = (((size_t)b*64 + cg*8 + cl)*IMG + y0+ty)*IMG + x0+tx;
        out[oi] = RESID ? (a + resid[oi]) : a;
    }
}

// ---------------------------------------------------------------------------
// Softmax over H (axis 2 of [B,72,H,W]) in place.
// ---------------------------------------------------------------------------
__global__ void softmaxH_kernel(float* __restrict__ a)
{
    const int tx = threadIdx.x, ty = threadIdx.y;
    const int w = blockIdx.x*32 + tx;
    const size_t base = (size_t)blockIdx.y * HWSZ + w;   // blockIdx.y = b*72+cc
    float vals[16];
    float mx = -3.4e38f;
    #pragma unroll
    for (int i = 0; i < 16; i++) {
        vals[i] = a[base + (size_t)(ty*16 + i)*IMG];
        mx = fmaxf(mx, vals[i]);
    }
    __shared__ float red[8][32];
    red[ty][tx] = mx;
    __syncthreads();
    float m = red[0][tx];
    #pragma unroll
    for (int j = 1; j < 8; j++) m = fmaxf(m, red[j][tx]);
    __syncthreads();
    float s = 0.f;
    #pragma unroll
    for (int i = 0; i < 16; i++) { vals[i] = __expf(vals[i] - m); s += vals[i]; }
    red[ty][tx] = s;
    __syncthreads();
    float tot = 0.f;
    #pragma unroll
    for (int j = 0; j < 8; j++) tot += red[j][tx];
    float inv = 1.f / tot;
    #pragma unroll
    for (int i = 0; i < 16; i++)
        a[base + (size_t)(ty*16 + i)*IMG] = vals[i]*inv;
}

// ---------------------------------------------------------------------------
extern "C" void kernel_launch(void* const* d_in, const int* in_sizes, int n_in,
                              void* d_out, int out_size)
{
    const float* x      = (const float*)d_in[0];
    const float* phi_w  = (const float*)d_in[1];
    const float* phi_b  = (const float*)d_in[2];
    const float* theta_w= (const float*)d_in[3];
    const float* theta_b= (const float*)d_in[4];
    const float* ke_w   = (const float*)d_in[5];
    const float* e1_w   = (const float*)d_in[6];
    const float* e2_w   = (const float*)d_in[7];
    const float* e2_b   = (const float*)d_in[8];
    const float* c1_w   = (const float*)d_in[9];
    const float* sw1_w  = (const float*)d_in[10];
    const float* sw2_w  = (const float*)d_in[11];
    const float* sw2_b  = (const float*)d_in[12];
    const float* sec_w  = (const float*)d_in[13];
    const float* sec_b  = (const float*)d_in[14];
    float* out = (float*)d_out;

    float* base = nullptr;
    cudaGetSymbolAddress((void**)&base, g_scratch);
    float* slotA = base;                 // q, then lc
    float* slotB = base + BUF64;         // keypre, then v, then u
    float* key   = base + 2*BUF64;       // live whole pipeline
    float* t32   = base + 3*BUF64;       // embed hidden (used twice)
    float* slotW = t32 + BUF32;          // w72, then attn

    float* q      = slotA;
    float* lc     = slotA;
    float* keypre = slotB;
    float* v      = slotB;
    float* u      = slotB;
    float* w72    = slotW;
    float* attn   = slotW;

    dim3 g256(64, 8, 1);   // 256-pixel tiles x batch
    // key_pre = phi(x), query = theta(x)
    conv1x1v2_kernel<64,64,64,0><<<g256,256>>>(keypre, x, nullptr, phi_w, phi_b, 64);
    conv1x1v2_kernel<64,64,64,0><<<g256,256>>>(q,      x, nullptr, theta_w, theta_b, 64);
    // key = lrelu(grouped 3x3(key_pre))
    convke_kernel<<<dim3(8,8,32),256>>>(key, keypre, ke_w);
    // dynamic kernel 1: w72 = e2(lrelu(e1([query;key])))   (q dead after this)
    conv1x1v2_kernel<128,32,64,1><<<g256,128>>>(t32, q, key, e1_w, nullptr, 32);
    conv1x1v2_kernel<32,72,32,0><<<g256,288>>>(w72, t32, nullptr, e2_w, e2_b, 72);
    // h(first half) = local_conv(c1(x), w72)   (keypre dead; v reuses slotB)
    conv1x1v2_kernel<64,64,64,0><<<g256,256>>>(v, x, nullptr, c1_w, nullptr, 64);
    localconv_kernel<false><<<dim3(8,8,64),256>>>(lc, v, w72, nullptr);
    // attention weights: attn = softmax_H(sw2(lrelu(sw1([lc;key]))))
    conv1x1v2_kernel<128,32,64,1><<<g256,128>>>(t32, lc, key, sw1_w, nullptr, 32);
    conv1x1v2_kernel<32,72,32,0><<<g256,288>>>(attn, t32, nullptr, sw2_w, sw2_b, 72);
    softmaxH_kernel<<<dim3(4, 8*72), dim3(32,8)>>>(attn);
    // out = local_conv(sec([lc;key]), attn) + x   (v dead; u reuses slotB)
    conv1x1v2_kernel<128,64,64,0><<<g256,256>>>(u, lc, key, sec_w, sec_b, 64);
    localconv_kernel<true><<<dim3(8,8,64),256>>>(out, u, attn, x);
}